// round 12
// baseline (speedup 1.0000x reference)
#include <cuda_runtime.h>
#include <cuda_bf16.h>
#include <cstdint>

// Problem constants
#define N_TOK   16384
#define K_CODE  8192
#define DIM     64
#define DECAYF  0.99f
#define OMDF    0.01f
#define EPSF    1e-5f
#define BATCHF  32.0f

// Output layout (floats): concat (discrete, quantized, new_count, new_weight, new_codebook)
#define OFF_QUAN (134217728ULL)                 // N*K
#define OFF_CNT  (OFF_QUAN + 1048576ULL)        // + N*D
#define OFF_WGT  (OFF_CNT  + 8192ULL)           // + K
#define OFF_CB   (OFF_WGT  + 524288ULL)         // + K*D

#define TOK_TILE 128
#define CHUNK    64
#define KSPLIT   2
#define KSLICE   (K_CODE / KSPLIT)              // 4096
#define NCHUNK   (KSLICE / CHUNK)               // 64
#define CAP      384
#define THRESH   4.5f

// Scratch (device globals; allocation-free rule)
__device__ __align__(16) __nv_bfloat16 g_Abf[N_TOK * DIM];
__device__ __align__(16) __nv_bfloat16 g_Bbf[K_CODE * DIM];   // holds bf16(-2 * codebook)
__device__ float g_cnorm[K_CODE];
__device__ int   g_idx[N_TOK];
__device__ float g_count[K_CODE];
__device__ float g_sum[K_CODE * DIM];
__device__ int   g_ccnt[N_TOK];
__device__ int   g_cand[N_TOK * CAP];

// ---------------------------------------------------------------------------
__device__ __forceinline__ uint32_t smem_u32(const void* p) {
    uint32_t a;
    asm("{ .reg .u64 t; cvta.to.shared.u64 t, %1; cvt.u32.u64 %0, t; }" : "=r"(a) : "l"(p));
    return a;
}
__device__ __forceinline__ void cp_async16(uint32_t dst, const void* src) {
    asm volatile("cp.async.cg.shared.global [%0], [%1], 16;" :: "r"(dst), "l"(src) : "memory");
}
#define CP_COMMIT() asm volatile("cp.async.commit_group;" ::: "memory")
#define CP_WAIT(n)  asm volatile("cp.async.wait_group %0;" :: "n"(n) : "memory")

__device__ __forceinline__ void ldm_x4(uint32_t& r0, uint32_t& r1, uint32_t& r2, uint32_t& r3,
                                       uint32_t addr) {
    asm volatile("ldmatrix.sync.aligned.m8n8.x4.shared.b16 {%0,%1,%2,%3}, [%4];"
                 : "=r"(r0), "=r"(r1), "=r"(r2), "=r"(r3) : "r"(addr));
}
__device__ __forceinline__ void mma16816(float* c, const uint32_t* a, uint32_t b0, uint32_t b1) {
    asm volatile("mma.sync.aligned.m16n8k16.row.col.f32.bf16.bf16.f32 "
                 "{%0,%1,%2,%3}, {%4,%5,%6,%7}, {%8,%9}, {%0,%1,%2,%3};"
                 : "+f"(c[0]), "+f"(c[1]), "+f"(c[2]), "+f"(c[3])
                 : "r"(a[0]), "r"(a[1]), "r"(a[2]), "r"(a[3]), "r"(b0), "r"(b1));
}

// ---------------------------------------------------------------------------
// Prep kernels
__global__ void prep_x_kernel(const float* __restrict__ x) {
    int i = blockIdx.x * blockDim.x + threadIdx.x;
    if (i < N_TOK * DIM) {
        g_Abf[i] = __float2bfloat16(x[i]);
        if (i < N_TOK) g_ccnt[i] = 0;
    }
}
// B holds bf16(-2*c): exact 2x scaling of bf16(-c); products are exactly -2x,
// so approx scores (cnorm + dot) match the previous (cnorm - 2*dot) bit-for-bit
// up to fp32 accumulation order; band bound unchanged.
__global__ void prep_c_kernel(const float* __restrict__ cb) {
    int i = blockIdx.x * blockDim.x + threadIdx.x;
    if (i < K_CODE * DIM) {
        g_Bbf[i] = __float2bfloat16(-2.0f * cb[i]);
        g_sum[i] = 0.0f;
        if (i < K_CODE) g_count[i] = 0.0f;
    }
}
__global__ void cnorm_kernel(const float* __restrict__ cb) {
    int w = (blockIdx.x * blockDim.x + threadIdx.x) >> 5;
    int lane = threadIdx.x & 31;
    if (w < K_CODE) {
        float v0 = cb[w * DIM + lane];
        float v1 = cb[w * DIM + 32 + lane];
        float s = v0 * v0 + v1 * v1;
        #pragma unroll
        for (int o = 16; o; o >>= 1) s += __shfl_xor_sync(0xFFFFFFFFu, s, o);
        if (lane == 0) g_cnorm[w] = s;
    }
}

// ---------------------------------------------------------------------------
// Pass 1: barrier-free HMMA GEMM + approx argmin band -> candidate lists.
// Grid = 128 token-blocks x 2 K-slices = 256 CTAs, 256 thr (8 warps = 4M x 2N).
// Warp tile 32x32. A fragments register-resident. B = -2c via per-warp private
// 3-slot cp.async ring. Accumulators initialized with cnorm -> acc IS the score.
// Lane-local running best (stale-valid band) -> zero shuffles in the epilogue.
#define B_SLOT  4096
#define P1_SMEM (8 * 3 * B_SLOT)   // 96KB -> 2 CTAs/SM

__device__ __forceinline__ uint32_t sw_off(int row, int c) {
    return (uint32_t)(row * 128 + ((c ^ (row & 7)) << 4));
}

// Per-warp prefetch of its own 32-row B sub-tile (4KB): 8 cp.async per lane
__device__ __forceinline__ void prefetch_B_warp(uint32_t dst, int krow0, int lane) {
    const char* src = (const char*)(g_Bbf) + (size_t)krow0 * 128;
    #pragma unroll
    for (int t = 0; t < 8; t++) {
        int j = lane + t * 32;          // 0..255 16B-chunks
        int row = j >> 3, c = j & 7;
        cp_async16(dst + sw_off(row, c), src + row * 128 + c * 16);
    }
    CP_COMMIT();
}

extern "C" __global__ void __launch_bounds__(256, 2)
gemm_cand_kernel() {
    extern __shared__ unsigned char smem[];
    const uint32_t sbase = smem_u32(smem);
    const int tid   = threadIdx.x;
    const int wid   = tid >> 5;
    const int lane  = tid & 31;
    const int warpM = wid >> 1;          // 0..3
    const int warpN = wid & 1;           // 0..1
    const int g     = lane >> 2;         // row group 0..7
    const int q     = lane & 3;          // col group 0..3
    const int lr    = lane & 15;
    const int lc    = lane >> 4;
    const int tb    = blockIdx.x & 127;             // token block
    const int slice = blockIdx.x >> 7;              // k slice 0..1
    const int kslice0 = slice * KSLICE;
    const int tokBase = tb * TOK_TILE + warpM * 32;
    const uint32_t ring = sbase + (uint32_t)(wid * 3) * B_SLOT;

    // Prolog: prefetch my B rows for chunks 0,1
    prefetch_B_warp(ring,          kslice0 + warpN * 32,         lane);
    prefetch_B_warp(ring + B_SLOT, kslice0 + CHUNK + warpN * 32, lane);

    // A fragments: resident in registers for all 64 chunks.
    uint32_t afrag[2][4][4];
    {
        const __nv_bfloat16* Ab = g_Abf + (size_t)(tb * TOK_TILE) * DIM;
        #pragma unroll
        for (int mi = 0; mi < 2; mi++)
            #pragma unroll
            for (int ks = 0; ks < 4; ks++) {
                int R = warpM * 32 + mi * 16 + (lane >> 2);
                int C = ks * 16 + (lane & 3) * 2;
                afrag[mi][ks][0] = *(const uint32_t*)(Ab + (size_t)R * DIM + C);
                afrag[mi][ks][1] = *(const uint32_t*)(Ab + (size_t)(R + 8) * DIM + C);
                afrag[mi][ks][2] = *(const uint32_t*)(Ab + (size_t)R * DIM + C + 8);
                afrag[mi][ks][3] = *(const uint32_t*)(Ab + (size_t)(R + 8) * DIM + C + 8);
            }
    }

    float rb[4] = {3.4e38f, 3.4e38f, 3.4e38f, 3.4e38f};   // lane-local running best

    for (int ci = 0; ci < NCHUNK; ci++) {
        // Keep group-count invariant: always commit exactly one group per iter
        if (ci + 2 < NCHUNK)
            prefetch_B_warp(ring + ((ci + 2) % 3) * B_SLOT,
                            kslice0 + (ci + 2) * CHUNK + warpN * 32, lane);
        else
            CP_COMMIT();

        const int kchunk = kslice0 + ci * CHUNK;

        // Init accumulators with cnorm: acc after MMA = cnorm + dot(x, -2c) = score
        float acc[2][4][4];
        {
            #pragma unroll
            for (int ni = 0; ni < 4; ni++) {
                int col = kchunk + warpN * 32 + ni * 8 + q * 2;
                float2 cn = __ldg((const float2*)(g_cnorm + col));
                #pragma unroll
                for (int mi = 0; mi < 2; mi++) {
                    acc[mi][ni][0] = cn.x; acc[mi][ni][1] = cn.y;
                    acc[mi][ni][2] = cn.x; acc[mi][ni][3] = cn.y;
                }
            }
        }

        CP_WAIT(2);          // chunk ci's data complete (per-thread groups)
        __syncwarp();        // cross-lane smem visibility within the warp

        const uint32_t Bs = ring + (ci % 3) * B_SLOT;

        #pragma unroll
        for (int ks = 0; ks < 4; ks++) {
            uint32_t b[2][4];
            #pragma unroll
            for (int nt = 0; nt < 2; nt++) {
                int row = nt * 16 + lr;             // local row in my 32-row tile
                ldm_x4(b[nt][0], b[nt][1], b[nt][2], b[nt][3],
                       Bs + sw_off(row, ks * 2 + lc));
            }
            #pragma unroll
            for (int mi = 0; mi < 2; mi++)
                #pragma unroll
                for (int ni = 0; ni < 4; ni++) {
                    int nt = ni >> 1, od = ni & 1;
                    mma16816(acc[mi][ni], afrag[mi][ks], b[nt][od], b[nt][od + 2]);
                }
        }

        // Lean epilogue: lane-local min over this chunk's 8 values per row,
        // lane-local running best (stale-valid), predicated appends. No shfl.
        #pragma unroll
        for (int mi = 0; mi < 2; mi++) {
            #pragma unroll
            for (int h = 0; h < 2; h++) {
                float m8 = fminf(fminf(fminf(acc[mi][0][2*h], acc[mi][0][2*h+1]),
                                       fminf(acc[mi][1][2*h], acc[mi][1][2*h+1])),
                                 fminf(fminf(acc[mi][2][2*h], acc[mi][2][2*h+1]),
                                       fminf(acc[mi][3][2*h], acc[mi][3][2*h+1])));
                float rbv = fminf(rb[mi * 2 + h], m8);
                rb[mi * 2 + h] = rbv;
                float lim = rbv + THRESH;
                if (m8 < lim) {
                    int tok = tokBase + mi * 16 + h * 8 + g;
                    #pragma unroll
                    for (int ni = 0; ni < 4; ni++) {
                        int k0 = kchunk + warpN * 32 + ni * 8 + q * 2;
                        float s0 = acc[mi][ni][2 * h], s1 = acc[mi][ni][2 * h + 1];
                        if (s0 < lim) {
                            int sl = atomicAdd(&g_ccnt[tok], 1);
                            if (sl < CAP) g_cand[tok * CAP + sl] = k0;
                        }
                        if (s1 < lim) {
                            int sl = atomicAdd(&g_ccnt[tok], 1);
                            if (sl < CAP) g_cand[tok * CAP + sl] = k0 + 1;
                        }
                    }
                }
            }
        }
    }
}

// ---------------------------------------------------------------------------
// Pass 2: exact fp32 refine over candidates (one warp per token)
__global__ void __launch_bounds__(256)
refine_kernel(const float* __restrict__ x, const float* __restrict__ cb) {
    __shared__ float sx[8][64];
    const int wid = threadIdx.x >> 5, lane = threadIdx.x & 31;
    const int tok = blockIdx.x * 8 + wid;
    sx[wid][lane]      = x[tok * DIM + lane];
    sx[wid][lane + 32] = x[tok * DIM + 32 + lane];
    __syncwarp();

    int cnt = g_ccnt[tok];
    float bd = 3.4e38f;
    int   bi = 0x7fffffff;

    if (cnt <= CAP) {
        for (int i = lane; i < cnt; i += 32) {
            int k = g_cand[tok * CAP + i];
            const float4* cr = (const float4*)(cb + k * DIM);
            float a = 0.0f;
            #pragma unroll
            for (int j = 0; j < 16; j++) {
                float4 c4 = __ldg(cr + j);
                a = fmaf(sx[wid][4 * j],     c4.x, a);
                a = fmaf(sx[wid][4 * j + 1], c4.y, a);
                a = fmaf(sx[wid][4 * j + 2], c4.z, a);
                a = fmaf(sx[wid][4 * j + 3], c4.w, a);
            }
            float d = fmaf(-2.0f, a, g_cnorm[k]);
            if (d < bd || (d == bd && k < bi)) { bd = d; bi = k; }
        }
    } else {
        for (int k = lane; k < K_CODE; k += 32) {
            const float4* cr = (const float4*)(cb + k * DIM);
            float a = 0.0f;
            #pragma unroll
            for (int j = 0; j < 16; j++) {
                float4 c4 = __ldg(cr + j);
                a = fmaf(sx[wid][4 * j],     c4.x, a);
                a = fmaf(sx[wid][4 * j + 1], c4.y, a);
                a = fmaf(sx[wid][4 * j + 2], c4.z, a);
                a = fmaf(sx[wid][4 * j + 3], c4.w, a);
            }
            float d = fmaf(-2.0f, a, g_cnorm[k]);
            if (d < bd || (d == bd && k < bi)) { bd = d; bi = k; }
        }
    }
    #pragma unroll
    for (int off = 16; off; off >>= 1) {
        float od = __shfl_xor_sync(0xFFFFFFFFu, bd, off);
        int   oi = __shfl_xor_sync(0xFFFFFFFFu, bi, off);
        if (od < bd || (od == bd && oi < bi)) { bd = od; bi = oi; }
    }
    if (lane == 0) g_idx[tok] = bi;
}

// ---------------------------------------------------------------------------
__global__ void fill_zero_kernel(float4* __restrict__ out, size_t n4) {
    size_t i = (size_t)blockIdx.x * blockDim.x + threadIdx.x;
    size_t stride = (size_t)gridDim.x * blockDim.x;
    float4 z = make_float4(0.f, 0.f, 0.f, 0.f);
    for (; i < n4; i += stride) out[i] = z;
}

__global__ void scatter_kernel(const float* __restrict__ x,
                               const float* __restrict__ cb,
                               float* __restrict__ out) {
    int n = blockIdx.x;
    int d = threadIdx.x;
    int k = g_idx[n];
    float xv = x[n * DIM + d];
    out[OFF_QUAN + (size_t)n * DIM + d] = cb[k * DIM + d];
    atomicAdd(&g_sum[k * DIM + d], xv);
    if (d == 0) {
        atomicAdd(&g_count[k], 1.0f);
        out[(size_t)n * K_CODE + k] = 1.0f;
    }
}

__global__ void finalize_kernel(const float* __restrict__ ema_count,
                                const float* __restrict__ ema_weight,
                                float* __restrict__ out) {
    int i = blockIdx.x * blockDim.x + threadIdx.x;
    if (i < K_CODE * DIM) {
        int k = i >> 6;
        float nw = ema_weight[i] * DECAYF + g_sum[i] * OMDF;
        float nc = ema_count[k] * DECAYF + g_count[k] * OMDF;
        nc = (nc + EPSF) / (BATCHF + (float)K_CODE * EPSF) * BATCHF;
        out[OFF_WGT + i] = nw;
        out[OFF_CB  + i] = nw / nc;
        if ((i & (DIM - 1)) == 0) out[OFF_CNT + k] = nc;
    }
}

// ---------------------------------------------------------------------------
extern "C" void kernel_launch(void* const* d_in, const int* in_sizes, int n_in,
                              void* d_out, int out_size) {
    const float* x    = (const float*)d_in[0];
    const float* cb   = (const float*)d_in[1];
    const float* ecnt = (const float*)d_in[2];
    const float* ewgt = (const float*)d_in[3];
    float* out = (float*)d_out;

    // One-time side stream + events (created on first, non-captured call).
    static cudaStream_t s_side = nullptr;
    static cudaEvent_t  s_fork = nullptr, s_join = nullptr;
    if (s_side == nullptr) {
        cudaStreamCreateWithFlags(&s_side, cudaStreamNonBlocking);
        cudaEventCreateWithFlags(&s_fork, cudaEventDisableTiming);
        cudaEventCreateWithFlags(&s_join, cudaEventDisableTiming);
    }

    cudaFuncSetAttribute(gemm_cand_kernel,
                         cudaFuncAttributeMaxDynamicSharedMemorySize, P1_SMEM);

    // Fork: zero-fill of the 536MB one-hot region on the side stream
    cudaEventRecord(s_fork, 0);
    cudaStreamWaitEvent(s_side, s_fork, 0);
    fill_zero_kernel<<<16384, 256, 0, s_side>>>((float4*)out, 33554432ULL);
    cudaEventRecord(s_join, s_side);

    // Main path
    prep_x_kernel<<<(N_TOK * DIM) / 256, 256>>>(x);
    prep_c_kernel<<<(K_CODE * DIM) / 256, 256>>>(cb);
    cnorm_kernel<<<(K_CODE * 32) / 256, 256>>>(cb);

    gemm_cand_kernel<<<128 * KSPLIT, 256, P1_SMEM>>>();
    refine_kernel<<<N_TOK / 8, 256>>>(x, cb);

    // Join: scatter writes into the zero-filled region
    cudaStreamWaitEvent(0, s_join, 0);
    scatter_kernel<<<N_TOK, DIM>>>(x, cb, out);
    finalize_kernel<<<(K_CODE * DIM) / 256, 256>>>(ecnt, ewgt, out);
}

// round 13
// speedup vs baseline: 1.7381x; 1.7381x over previous
#include <cuda_runtime.h>
#include <cuda_bf16.h>
#include <cstdint>

// Problem constants
#define N_TOK   16384
#define K_CODE  8192
#define DIM     64
#define DECAYF  0.99f
#define OMDF    0.01f
#define EPSF    1e-5f
#define BATCHF  32.0f

// Output layout (floats): concat (discrete, quantized, new_count, new_weight, new_codebook)
#define OFF_QUAN (134217728ULL)                 // N*K
#define OFF_CNT  (OFF_QUAN + 1048576ULL)        // + N*D
#define OFF_WGT  (OFF_CNT  + 8192ULL)           // + K
#define OFF_CB   (OFF_WGT  + 524288ULL)         // + K*D

#define TOK_TILE 128
#define CHUNK    64
#define KSPLIT   2
#define KSLICE   (K_CODE / KSPLIT)              // 4096
#define NCHUNK   (KSLICE / CHUNK)               // 64
#define CAP      384
#define THRESH   4.5f

// Scratch (device globals; allocation-free rule)
__device__ __align__(16) __nv_bfloat16 g_Abf[N_TOK * DIM];
__device__ __align__(16) __nv_bfloat16 g_Bbf[K_CODE * DIM];   // holds bf16(-2 * codebook)
__device__ float g_cnorm[K_CODE];
__device__ int   g_idx[N_TOK];
__device__ float g_count[K_CODE];
__device__ float g_sum[K_CODE * DIM];
__device__ int   g_ccnt[N_TOK];
__device__ int   g_cand[N_TOK * CAP];

// ---------------------------------------------------------------------------
__device__ __forceinline__ uint32_t smem_u32(const void* p) {
    uint32_t a;
    asm("{ .reg .u64 t; cvta.to.shared.u64 t, %1; cvt.u32.u64 %0, t; }" : "=r"(a) : "l"(p));
    return a;
}
__device__ __forceinline__ void cp_async16(uint32_t dst, const void* src) {
    asm volatile("cp.async.cg.shared.global [%0], [%1], 16;" :: "r"(dst), "l"(src) : "memory");
}
#define CP_COMMIT() asm volatile("cp.async.commit_group;" ::: "memory")
#define CP_WAIT(n)  asm volatile("cp.async.wait_group %0;" :: "n"(n) : "memory")

__device__ __forceinline__ void ldm_x4(uint32_t& r0, uint32_t& r1, uint32_t& r2, uint32_t& r3,
                                       uint32_t addr) {
    asm volatile("ldmatrix.sync.aligned.m8n8.x4.shared.b16 {%0,%1,%2,%3}, [%4];"
                 : "=r"(r0), "=r"(r1), "=r"(r2), "=r"(r3) : "r"(addr));
}
__device__ __forceinline__ void mma16816(float* c, const uint32_t* a, uint32_t b0, uint32_t b1) {
    asm volatile("mma.sync.aligned.m16n8k16.row.col.f32.bf16.bf16.f32 "
                 "{%0,%1,%2,%3}, {%4,%5,%6,%7}, {%8,%9}, {%0,%1,%2,%3};"
                 : "+f"(c[0]), "+f"(c[1]), "+f"(c[2]), "+f"(c[3])
                 : "r"(a[0]), "r"(a[1]), "r"(a[2]), "r"(a[3]), "r"(b0), "r"(b1));
}

// ---------------------------------------------------------------------------
// Prep kernels
__global__ void prep_x_kernel(const float* __restrict__ x) {
    int i = blockIdx.x * blockDim.x + threadIdx.x;
    if (i < N_TOK * DIM) {
        g_Abf[i] = __float2bfloat16(x[i]);
        if (i < N_TOK) g_ccnt[i] = 0;
    }
}
// B holds bf16(-2*c): exact 2x scaling of bf16(-c); scores come out of the MMA
// directly as cnorm + dot(x, -2c), same values as before up to fp32 ordering.
__global__ void prep_c_kernel(const float* __restrict__ cb) {
    int i = blockIdx.x * blockDim.x + threadIdx.x;
    if (i < K_CODE * DIM) {
        g_Bbf[i] = __float2bfloat16(-2.0f * cb[i]);
        g_sum[i] = 0.0f;
        if (i < K_CODE) g_count[i] = 0.0f;
    }
}
__global__ void cnorm_kernel(const float* __restrict__ cb) {
    int w = (blockIdx.x * blockDim.x + threadIdx.x) >> 5;
    int lane = threadIdx.x & 31;
    if (w < K_CODE) {
        float v0 = cb[w * DIM + lane];
        float v1 = cb[w * DIM + 32 + lane];
        float s = v0 * v0 + v1 * v1;
        #pragma unroll
        for (int o = 16; o; o >>= 1) s += __shfl_xor_sync(0xFFFFFFFFu, s, o);
        if (lane == 0) g_cnorm[w] = s;
    }
}

// ---------------------------------------------------------------------------
// Pass 1: barrier-free HMMA GEMM + approx argmin band -> candidate lists.
// Grid = 128 token-blocks x 2 K-slices = 256 CTAs, 256 thr (8 warps = 4M x 2N).
// Warp tile 32x32. A fragments register-resident. B = -2c via per-warp private
// 3-slot cp.async ring. Accumulators initialized with cnorm -> acc IS the score.
// Epilogue: R11's warp-shuffled row-best band (tight band; this is what keeps
// candidate counts low -- R12's lane-local band caused CAP overflow blowups).
#define B_SLOT  4096
#define P1_SMEM (8 * 3 * B_SLOT)   // 96KB -> 2 CTAs/SM

__device__ __forceinline__ uint32_t sw_off(int row, int c) {
    return (uint32_t)(row * 128 + ((c ^ (row & 7)) << 4));
}

// Per-warp prefetch of its own 32-row B sub-tile (4KB): 8 cp.async per lane
__device__ __forceinline__ void prefetch_B_warp(uint32_t dst, int krow0, int lane) {
    const char* src = (const char*)(g_Bbf) + (size_t)krow0 * 128;
    #pragma unroll
    for (int t = 0; t < 8; t++) {
        int j = lane + t * 32;          // 0..255 16B-chunks
        int row = j >> 3, c = j & 7;
        cp_async16(dst + sw_off(row, c), src + row * 128 + c * 16);
    }
    CP_COMMIT();
}

extern "C" __global__ void __launch_bounds__(256, 2)
gemm_cand_kernel() {
    extern __shared__ unsigned char smem[];
    const uint32_t sbase = smem_u32(smem);
    const int tid   = threadIdx.x;
    const int wid   = tid >> 5;
    const int lane  = tid & 31;
    const int warpM = wid >> 1;          // 0..3
    const int warpN = wid & 1;           // 0..1
    const int g     = lane >> 2;         // row group 0..7
    const int q     = lane & 3;          // col group 0..3
    const int lr    = lane & 15;
    const int lc    = lane >> 4;
    const int tb    = blockIdx.x & 127;             // token block
    const int slice = blockIdx.x >> 7;              // k slice 0..1
    const int kslice0 = slice * KSLICE;
    const int tokBase = tb * TOK_TILE + warpM * 32;
    const uint32_t ring = sbase + (uint32_t)(wid * 3) * B_SLOT;

    // Prolog: prefetch my B rows for chunks 0,1
    prefetch_B_warp(ring,          kslice0 + warpN * 32,         lane);
    prefetch_B_warp(ring + B_SLOT, kslice0 + CHUNK + warpN * 32, lane);

    // A fragments: resident in registers for all 64 chunks.
    uint32_t afrag[2][4][4];
    {
        const __nv_bfloat16* Ab = g_Abf + (size_t)(tb * TOK_TILE) * DIM;
        #pragma unroll
        for (int mi = 0; mi < 2; mi++)
            #pragma unroll
            for (int ks = 0; ks < 4; ks++) {
                int R = warpM * 32 + mi * 16 + (lane >> 2);
                int C = ks * 16 + (lane & 3) * 2;
                afrag[mi][ks][0] = *(const uint32_t*)(Ab + (size_t)R * DIM + C);
                afrag[mi][ks][1] = *(const uint32_t*)(Ab + (size_t)(R + 8) * DIM + C);
                afrag[mi][ks][2] = *(const uint32_t*)(Ab + (size_t)R * DIM + C + 8);
                afrag[mi][ks][3] = *(const uint32_t*)(Ab + (size_t)(R + 8) * DIM + C + 8);
            }
    }

    float rb[4] = {3.4e38f, 3.4e38f, 3.4e38f, 3.4e38f};   // warp-shared row running best

    for (int ci = 0; ci < NCHUNK; ci++) {
        // Keep group-count invariant: always commit exactly one group per iter
        if (ci + 2 < NCHUNK)
            prefetch_B_warp(ring + ((ci + 2) % 3) * B_SLOT,
                            kslice0 + (ci + 2) * CHUNK + warpN * 32, lane);
        else
            CP_COMMIT();

        const int kchunk = kslice0 + ci * CHUNK;

        // Init accumulators with cnorm: acc after MMA = cnorm + dot(x, -2c) = score
        float acc[2][4][4];
        {
            #pragma unroll
            for (int ni = 0; ni < 4; ni++) {
                int col = kchunk + warpN * 32 + ni * 8 + q * 2;
                float2 cn = __ldg((const float2*)(g_cnorm + col));
                #pragma unroll
                for (int mi = 0; mi < 2; mi++) {
                    acc[mi][ni][0] = cn.x; acc[mi][ni][1] = cn.y;
                    acc[mi][ni][2] = cn.x; acc[mi][ni][3] = cn.y;
                }
            }
        }

        CP_WAIT(2);          // chunk ci's data complete (per-thread groups)
        __syncwarp();        // cross-lane smem visibility within the warp

        const uint32_t Bs = ring + (ci % 3) * B_SLOT;

        #pragma unroll
        for (int ks = 0; ks < 4; ks++) {
            uint32_t b[2][4];
            #pragma unroll
            for (int nt = 0; nt < 2; nt++) {
                int row = nt * 16 + lr;             // local row in my 32-row tile
                ldm_x4(b[nt][0], b[nt][1], b[nt][2], b[nt][3],
                       Bs + sw_off(row, ks * 2 + lc));
            }
            #pragma unroll
            for (int mi = 0; mi < 2; mi++)
                #pragma unroll
                for (int ni = 0; ni < 4; ni++) {
                    int nt = ni >> 1, od = ni & 1;
                    mma16816(acc[mi][ni], afrag[mi][ks], b[nt][od], b[nt][od + 2]);
                }
        }

        // R11 epilogue: row-min across the 4 q-lanes (tight band), running best,
        // __any_sync skip guard, predicated appends.
        #pragma unroll
        for (int mi = 0; mi < 2; mi++) {
            #pragma unroll
            for (int h = 0; h < 2; h++) {
                float cm = fminf(fminf(fminf(acc[mi][0][2*h], acc[mi][0][2*h+1]),
                                       fminf(acc[mi][1][2*h], acc[mi][1][2*h+1])),
                                 fminf(fminf(acc[mi][2][2*h], acc[mi][2][2*h+1]),
                                       fminf(acc[mi][3][2*h], acc[mi][3][2*h+1])));
                cm = fminf(cm, __shfl_xor_sync(0xFFFFFFFFu, cm, 1));
                cm = fminf(cm, __shfl_xor_sync(0xFFFFFFFFu, cm, 2));
                float rbv = fminf(rb[mi * 2 + h], cm);
                rb[mi * 2 + h] = rbv;
                float lim = rbv + THRESH;
                if (__any_sync(0xFFFFFFFFu, cm < lim)) {
                    int tok = tokBase + mi * 16 + h * 8 + g;
                    #pragma unroll
                    for (int ni = 0; ni < 4; ni++) {
                        int k0 = kchunk + warpN * 32 + ni * 8 + q * 2;
                        float s0 = acc[mi][ni][2 * h], s1 = acc[mi][ni][2 * h + 1];
                        if (s0 < lim) {
                            int sl = atomicAdd(&g_ccnt[tok], 1);
                            if (sl < CAP) g_cand[tok * CAP + sl] = k0;
                        }
                        if (s1 < lim) {
                            int sl = atomicAdd(&g_ccnt[tok], 1);
                            if (sl < CAP) g_cand[tok * CAP + sl] = k0 + 1;
                        }
                    }
                }
            }
        }
    }
}

// ---------------------------------------------------------------------------
// Pass 2: exact fp32 refine over candidates (one warp per token)
__global__ void __launch_bounds__(256)
refine_kernel(const float* __restrict__ x, const float* __restrict__ cb) {
    __shared__ float sx[8][64];
    const int wid = threadIdx.x >> 5, lane = threadIdx.x & 31;
    const int tok = blockIdx.x * 8 + wid;
    sx[wid][lane]      = x[tok * DIM + lane];
    sx[wid][lane + 32] = x[tok * DIM + 32 + lane];
    __syncwarp();

    int cnt = g_ccnt[tok];
    float bd = 3.4e38f;
    int   bi = 0x7fffffff;

    if (cnt <= CAP) {
        for (int i = lane; i < cnt; i += 32) {
            int k = g_cand[tok * CAP + i];
            const float4* cr = (const float4*)(cb + k * DIM);
            float a = 0.0f;
            #pragma unroll
            for (int j = 0; j < 16; j++) {
                float4 c4 = __ldg(cr + j);
                a = fmaf(sx[wid][4 * j],     c4.x, a);
                a = fmaf(sx[wid][4 * j + 1], c4.y, a);
                a = fmaf(sx[wid][4 * j + 2], c4.z, a);
                a = fmaf(sx[wid][4 * j + 3], c4.w, a);
            }
            float d = fmaf(-2.0f, a, g_cnorm[k]);
            if (d < bd || (d == bd && k < bi)) { bd = d; bi = k; }
        }
    } else {
        for (int k = lane; k < K_CODE; k += 32) {
            const float4* cr = (const float4*)(cb + k * DIM);
            float a = 0.0f;
            #pragma unroll
            for (int j = 0; j < 16; j++) {
                float4 c4 = __ldg(cr + j);
                a = fmaf(sx[wid][4 * j],     c4.x, a);
                a = fmaf(sx[wid][4 * j + 1], c4.y, a);
                a = fmaf(sx[wid][4 * j + 2], c4.z, a);
                a = fmaf(sx[wid][4 * j + 3], c4.w, a);
            }
            float d = fmaf(-2.0f, a, g_cnorm[k]);
            if (d < bd || (d == bd && k < bi)) { bd = d; bi = k; }
        }
    }
    #pragma unroll
    for (int off = 16; off; off >>= 1) {
        float od = __shfl_xor_sync(0xFFFFFFFFu, bd, off);
        int   oi = __shfl_xor_sync(0xFFFFFFFFu, bi, off);
        if (od < bd || (od == bd && oi < bi)) { bd = od; bi = oi; }
    }
    if (lane == 0) g_idx[tok] = bi;
}

// ---------------------------------------------------------------------------
__global__ void fill_zero_kernel(float4* __restrict__ out, size_t n4) {
    size_t i = (size_t)blockIdx.x * blockDim.x + threadIdx.x;
    size_t stride = (size_t)gridDim.x * blockDim.x;
    float4 z = make_float4(0.f, 0.f, 0.f, 0.f);
    for (; i < n4; i += stride) out[i] = z;
}

__global__ void scatter_kernel(const float* __restrict__ x,
                               const float* __restrict__ cb,
                               float* __restrict__ out) {
    int n = blockIdx.x;
    int d = threadIdx.x;
    int k = g_idx[n];
    float xv = x[n * DIM + d];
    out[OFF_QUAN + (size_t)n * DIM + d] = cb[k * DIM + d];
    atomicAdd(&g_sum[k * DIM + d], xv);
    if (d == 0) {
        atomicAdd(&g_count[k], 1.0f);
        out[(size_t)n * K_CODE + k] = 1.0f;
    }
}

__global__ void finalize_kernel(const float* __restrict__ ema_count,
                                const float* __restrict__ ema_weight,
                                float* __restrict__ out) {
    int i = blockIdx.x * blockDim.x + threadIdx.x;
    if (i < K_CODE * DIM) {
        int k = i >> 6;
        float nw = ema_weight[i] * DECAYF + g_sum[i] * OMDF;
        float nc = ema_count[k] * DECAYF + g_count[k] * OMDF;
        nc = (nc + EPSF) / (BATCHF + (float)K_CODE * EPSF) * BATCHF;
        out[OFF_WGT + i] = nw;
        out[OFF_CB  + i] = nw / nc;
        if ((i & (DIM - 1)) == 0) out[OFF_CNT + k] = nc;
    }
}

// ---------------------------------------------------------------------------
extern "C" void kernel_launch(void* const* d_in, const int* in_sizes, int n_in,
                              void* d_out, int out_size) {
    const float* x    = (const float*)d_in[0];
    const float* cb   = (const float*)d_in[1];
    const float* ecnt = (const float*)d_in[2];
    const float* ewgt = (const float*)d_in[3];
    float* out = (float*)d_out;

    // One-time side stream + events (created on first, non-captured call).
    static cudaStream_t s_side = nullptr;
    static cudaEvent_t  s_fork = nullptr, s_join = nullptr;
    if (s_side == nullptr) {
        cudaStreamCreateWithFlags(&s_side, cudaStreamNonBlocking);
        cudaEventCreateWithFlags(&s_fork, cudaEventDisableTiming);
        cudaEventCreateWithFlags(&s_join, cudaEventDisableTiming);
    }

    cudaFuncSetAttribute(gemm_cand_kernel,
                         cudaFuncAttributeMaxDynamicSharedMemorySize, P1_SMEM);

    // Fork: zero-fill of the 536MB one-hot region on the side stream
    cudaEventRecord(s_fork, 0);
    cudaStreamWaitEvent(s_side, s_fork, 0);
    fill_zero_kernel<<<16384, 256, 0, s_side>>>((float4*)out, 33554432ULL);
    cudaEventRecord(s_join, s_side);

    // Main path
    prep_x_kernel<<<(N_TOK * DIM) / 256, 256>>>(x);
    prep_c_kernel<<<(K_CODE * DIM) / 256, 256>>>(cb);
    cnorm_kernel<<<(K_CODE * 32) / 256, 256>>>(cb);

    gemm_cand_kernel<<<128 * KSPLIT, 256, P1_SMEM>>>();
    refine_kernel<<<N_TOK / 8, 256>>>(x, cb);

    // Join: scatter writes into the zero-filled region
    cudaStreamWaitEvent(0, s_join, 0);
    scatter_kernel<<<N_TOK, DIM>>>(x, cb, out);
    finalize_kernel<<<(K_CODE * DIM) / 256, 256>>>(ecnt, ewgt, out);
}